// round 1
// baseline (speedup 1.0000x reference)
#include <cuda_runtime.h>
#include <cstdint>

// Problem sizes
#define GN 8192
#define GD 128

// Main GEMM tiling: M=8192, N=128, K=3*8192=24576
#define BM 64
#define BN 128
#define BK 32
#define NSTAGE 4
#define ASTR 36    // padded smem stride for A tile rows (conflict-free frag loads)
#define BSTR 136   // padded smem stride for B tile rows (conflict-free frag loads)
#define A_TILE (BM * ASTR)
#define B_TILE (BK * BSTR)
#define SMEM2 ((NSTAGE * (A_TILE + B_TILE)) * 4)

// Scratch: Y[s][row][col] = ((x * sd_s) @ W), tf32-rounded, fp32 storage. 12.6 MB.
__device__ float g_Y[3ull * GN * GD];

// ---------------------------------------------------------------------------
// helpers
// ---------------------------------------------------------------------------
__device__ __forceinline__ uint32_t f2tf32(float x) {
    uint32_t r;
    asm("cvt.rna.tf32.f32 %0, %1;" : "=r"(r) : "f"(x));
    return r;
}

__device__ __forceinline__ float f2tf32f(float x) {
    uint32_t r = f2tf32(x);
    return __uint_as_float(r);
}

__device__ __forceinline__ void cp_async16(void* smem_dst, const void* gsrc) {
    uint32_t s = (uint32_t)__cvta_generic_to_shared(smem_dst);
    asm volatile("cp.async.cg.shared.global [%0], [%1], 16;\n" ::"r"(s), "l"(gsrc));
}

__device__ __forceinline__ void cp_commit() {
    asm volatile("cp.async.commit_group;\n" ::);
}

template <int N>
__device__ __forceinline__ void cp_wait() {
    asm volatile("cp.async.wait_group %0;\n" ::"n"(N));
}

__device__ __forceinline__ void mma_m16n8k8_tf32(float d[4], const uint32_t a[4],
                                                 const uint32_t b[2]) {
    asm volatile(
        "mma.sync.aligned.m16n8k8.row.col.f32.tf32.tf32.f32 "
        "{%0,%1,%2,%3}, {%4,%5,%6,%7}, {%8,%9}, {%0,%1,%2,%3};\n"
        : "+f"(d[0]), "+f"(d[1]), "+f"(d[2]), "+f"(d[3])
        : "r"(a[0]), "r"(a[1]), "r"(a[2]), "r"(a[3]), "r"(b[0]), "r"(b[1]));
}

// ---------------------------------------------------------------------------
// Kernel 1: Y_s = (x * sd_s) @ W   for s in {0,1,2}
// grid = (128, 3), block = 256. Each block: 64 rows x 128 cols, K=128.
// ---------------------------------------------------------------------------
__global__ __launch_bounds__(256) void prep_kernel(
    const float* __restrict__ x, const float* __restrict__ W,
    const float* __restrict__ sd0, const float* __restrict__ sd1,
    const float* __restrict__ sd2) {
    __shared__ float Xs[64][36];   // [row][k], padded
    __shared__ float Ws[32][128];  // [k][col]

    const int s = blockIdx.y;
    const float* sd = (s == 0) ? sd0 : (s == 1) ? sd1 : sd2;
    const int row0 = blockIdx.x * 64;
    const int tid = threadIdx.x;
    const int tx = tid & 15;  // col group: cols tx*8 .. tx*8+7
    const int ty = tid >> 4;  // row group: rows ty*4 .. ty*4+3

    float acc[4][8];
#pragma unroll
    for (int i = 0; i < 4; i++)
#pragma unroll
        for (int j = 0; j < 8; j++) acc[i][j] = 0.f;

    for (int kt = 0; kt < 128; kt += 32) {
        __syncthreads();
// load x tile (scaled by sd): 64x32 = 2048 elems, 8 per thread
#pragma unroll
        for (int j = 0; j < 8; j++) {
            int idx = j * 256 + tid;
            int r = idx >> 5;
            int k = idx & 31;
            Xs[r][k] = x[(row0 + r) * GD + kt + k] * sd[kt + k];
        }
// load W tile: 32x128 = 4096 elems, 4 float4 per thread
#pragma unroll
        for (int j = 0; j < 4; j++) {
            int idx = j * 256 + tid;
            int r = idx >> 5;
            int c4 = (idx & 31) * 4;
            *(float4*)&Ws[r][c4] = *(const float4*)&W[(kt + r) * GD + c4];
        }
        __syncthreads();

#pragma unroll
        for (int k = 0; k < 32; k++) {
            float w[8];
            *(float4*)&w[0] = *(float4*)&Ws[k][tx * 8];
            *(float4*)&w[4] = *(float4*)&Ws[k][tx * 8 + 4];
#pragma unroll
            for (int i = 0; i < 4; i++) {
                float a = Xs[ty * 4 + i][k];
#pragma unroll
                for (int j = 0; j < 8; j++) acc[i][j] = fmaf(a, w[j], acc[i][j]);
            }
        }
    }

// write Y, rounded to tf32 so the main GEMM's B operand needs no cvt
#pragma unroll
    for (int i = 0; i < 4; i++) {
        int r = row0 + ty * 4 + i;
        float* dst = &g_Y[((size_t)s * GN + r) * GD + tx * 8];
#pragma unroll
        for (int j = 0; j < 8; j++) dst[j] = f2tf32f(acc[i][j]);
    }
}

// ---------------------------------------------------------------------------
// Kernel 2: out = relu( S0@Y0 + S1@Y1 + S2@Y2 )
// One GEMM, M=8192 (128 CTAs x BM=64), N=128, K=24576 (768 k-tiles of 32).
// tf32 mma.sync m16n8k8, 4-stage cp.async pipeline.
// 256 threads = 8 warps in 2(m) x 4(n); warp tile 32x32.
// ---------------------------------------------------------------------------
__global__ __launch_bounds__(256, 1) void main_gemm(
    const float* __restrict__ S0, const float* __restrict__ S1,
    const float* __restrict__ S2, float* __restrict__ out) {
    extern __shared__ float smem[];
    float* As = smem;                      // NSTAGE * BM * ASTR
    float* Bs = smem + NSTAGE * A_TILE;    // NSTAGE * BK * BSTR

    const int tid = threadIdx.x;
    const int block_row = blockIdx.x * BM;

    const int wid = tid >> 5;
    const int lane = tid & 31;
    const int warp_m = wid & 1;   // 0..1
    const int warp_n = wid >> 1;  // 0..3
    const int gid = lane >> 2;    // 0..7
    const int tig = lane & 3;     // 0..3
    const int m_base = warp_m * 32;
    const int n_base = warp_n * 32;

    float acc[2][4][4];
#pragma unroll
    for (int mi = 0; mi < 2; mi++)
#pragma unroll
        for (int ni = 0; ni < 4; ni++)
#pragma unroll
            for (int q = 0; q < 4; q++) acc[mi][ni][q] = 0.f;

    auto issue_loads = [&](int stage, int kt) {
        const int s = kt >> 8;                 // 256 k-tiles per support
        const int klocal = (kt & 255) << 5;    // *32
        const float* Ag = (s == 0) ? S0 : (s == 1) ? S1 : S2;
        Ag += (size_t)block_row * GN + klocal;
        const float* Bg = g_Y + ((size_t)s * GN + klocal) * GD;
        float* as = As + stage * A_TILE;
        float* bs = Bs + stage * B_TILE;
// A: 64 rows x 8 float4 = 512 cp.async -> 2 per thread
#pragma unroll
        for (int j = 0; j < 2; j++) {
            int idx = j * 256 + tid;
            int r = idx >> 3;
            int c4 = (idx & 7) * 4;
            cp_async16(&as[r * ASTR + c4], Ag + (size_t)r * GN + c4);
        }
// B: 32 rows x 32 float4 = 1024 cp.async -> 4 per thread
#pragma unroll
        for (int j = 0; j < 4; j++) {
            int idx = j * 256 + tid;
            int r = idx >> 5;
            int c4 = (idx & 31) * 4;
            cp_async16(&bs[r * BSTR + c4], Bg + r * GD + c4);
        }
    };

    auto compute_tile = [&](int stage) {
        const float* as = As + stage * A_TILE;
        const float* bs = Bs + stage * B_TILE;
#pragma unroll
        for (int kk = 0; kk < 4; kk++) {
            const int k0 = kk * 8;
            uint32_t a[2][4];
#pragma unroll
            for (int mi = 0; mi < 2; mi++) {
                int r = m_base + mi * 16 + gid;
                a[mi][0] = f2tf32(as[r * ASTR + k0 + tig]);
                a[mi][1] = f2tf32(as[(r + 8) * ASTR + k0 + tig]);
                a[mi][2] = f2tf32(as[r * ASTR + k0 + tig + 4]);
                a[mi][3] = f2tf32(as[(r + 8) * ASTR + k0 + tig + 4]);
            }
            uint32_t b[4][2];
#pragma unroll
            for (int ni = 0; ni < 4; ni++) {
                int c = n_base + ni * 8 + gid;
                b[ni][0] = __float_as_uint(bs[(k0 + tig) * BSTR + c]);
                b[ni][1] = __float_as_uint(bs[(k0 + tig + 4) * BSTR + c]);
            }
#pragma unroll
            for (int mi = 0; mi < 2; mi++)
#pragma unroll
                for (int ni = 0; ni < 4; ni++)
                    mma_m16n8k8_tf32(acc[mi][ni], a[mi], b[ni]);
        }
    };

    const int KT = 768;  // 3 * 8192 / 32

    // prologue: fill NSTAGE-1 stages
#pragma unroll
    for (int st = 0; st < NSTAGE - 1; st++) {
        issue_loads(st, st);
        cp_commit();
    }

    for (int kt = 0; kt < KT; kt++) {
        cp_wait<NSTAGE - 2>();
        __syncthreads();
        int nxt = kt + NSTAGE - 1;
        if (nxt < KT) issue_loads(nxt & (NSTAGE - 1), nxt);
        cp_commit();
        compute_tile(kt & (NSTAGE - 1));
    }

// epilogue: relu + store (float2 per pair of adjacent columns)
#pragma unroll
    for (int mi = 0; mi < 2; mi++) {
#pragma unroll
        for (int ni = 0; ni < 4; ni++) {
            int r = block_row + m_base + mi * 16 + gid;
            int c = n_base + ni * 8 + tig * 2;
            float2 v0, v1;
            v0.x = fmaxf(acc[mi][ni][0], 0.f);
            v0.y = fmaxf(acc[mi][ni][1], 0.f);
            v1.x = fmaxf(acc[mi][ni][2], 0.f);
            v1.y = fmaxf(acc[mi][ni][3], 0.f);
            *(float2*)&out[(size_t)r * GD + c] = v0;
            *(float2*)&out[(size_t)(r + 8) * GD + c] = v1;
        }
    }
}

// ---------------------------------------------------------------------------
// launch
// ---------------------------------------------------------------------------
extern "C" void kernel_launch(void* const* d_in, const int* in_sizes, int n_in,
                              void* d_out, int out_size) {
    const float* x = (const float*)d_in[0];
    const float* S0 = (const float*)d_in[1];
    const float* S1 = (const float*)d_in[2];
    const float* S2 = (const float*)d_in[3];
    const float* W = (const float*)d_in[4];
    const float* sd0 = (const float*)d_in[5];
    const float* sd1 = (const float*)d_in[6];
    const float* sd2 = (const float*)d_in[7];
    float* out = (float*)d_out;

    cudaFuncSetAttribute(main_gemm, cudaFuncAttributeMaxDynamicSharedMemorySize,
                         SMEM2);

    dim3 pgrid(GN / 64, 3);
    prep_kernel<<<pgrid, 256>>>(x, W, sd0, sd1, sd2);
    main_gemm<<<GN / BM, 256, SMEM2>>>(S0, S1, S2, out);
}

// round 3
// speedup vs baseline: 1.1571x; 1.1571x over previous
#include <cuda_runtime.h>
#include <cstdint>

// ---------------------------------------------------------------------------
// out = relu( S0@Y0 + S1@Y1 + S2@Y2 ),  Y_s = (x*sd_s)@W
// Main GEMM: M=8192, N=128, K=3*8192=24576, split-K=2 -> 256 CTAs (2/SM).
// Legacy mma.sync tf32 (tcgen05 PTX is rejected: harness targets plain sm_103).
// ---------------------------------------------------------------------------
#define GN 8192
#define GD 128
#define BM 64
#define BK 32
#define KSPLIT 2
#define KT_PER (GN * 3 / KSPLIT / BK)  // 384 k-tiles per CTA
#define NSTAGE 4
#define ASTR 36
#define BSTR 136
#define A_TILE (BM * ASTR)
#define B_TILE (BK * BSTR)
#define SMEM2 ((NSTAGE * (A_TILE + B_TILE)) * 4)  // 106,496 B per CTA

// Scratch (no allocation allowed)
__device__ float g_Y[3ull * GN * GD];                 // Y_s, tf32-rounded
__device__ float g_P[(size_t)KSPLIT * GN * GD];       // split-K partials

// ---------------------------------------------------------------------------
__device__ __forceinline__ uint32_t f2tf32(float x) {
    uint32_t r;
    asm("cvt.rna.tf32.f32 %0, %1;" : "=r"(r) : "f"(x));
    return r;
}
__device__ __forceinline__ float f2tf32f(float x) {
    return __uint_as_float(f2tf32(x));
}

__device__ __forceinline__ void cp_async16(void* smem_dst, const void* gsrc) {
    uint32_t s = (uint32_t)__cvta_generic_to_shared(smem_dst);
    asm volatile("cp.async.cg.shared.global [%0], [%1], 16;\n" ::"r"(s), "l"(gsrc));
}
__device__ __forceinline__ void cp_commit() {
    asm volatile("cp.async.commit_group;\n" ::);
}
template <int N>
__device__ __forceinline__ void cp_wait() {
    asm volatile("cp.async.wait_group %0;\n" ::"n"(N));
}

__device__ __forceinline__ void mma_m16n8k8_tf32(float d[4], const uint32_t a[4],
                                                 const uint32_t b[2]) {
    asm volatile(
        "mma.sync.aligned.m16n8k8.row.col.f32.tf32.tf32.f32 "
        "{%0,%1,%2,%3}, {%4,%5,%6,%7}, {%8,%9}, {%0,%1,%2,%3};\n"
        : "+f"(d[0]), "+f"(d[1]), "+f"(d[2]), "+f"(d[3])
        : "r"(a[0]), "r"(a[1]), "r"(a[2]), "r"(a[3]), "r"(b[0]), "r"(b[1]));
}

// ---------------------------------------------------------------------------
// Kernel 1: Y_s = (x * sd_s) @ W  (verified in round 1)
// grid = (128, 3), block = 256. Each block: 64 rows x 128 cols, K=128.
// ---------------------------------------------------------------------------
__global__ __launch_bounds__(256) void prep_kernel(
    const float* __restrict__ x, const float* __restrict__ W,
    const float* __restrict__ sd0, const float* __restrict__ sd1,
    const float* __restrict__ sd2) {
    __shared__ float Xs[64][36];
    __shared__ float Ws[32][128];

    const int s = blockIdx.y;
    const float* sd = (s == 0) ? sd0 : (s == 1) ? sd1 : sd2;
    const int row0 = blockIdx.x * 64;
    const int tid = threadIdx.x;
    const int tx = tid & 15;
    const int ty = tid >> 4;

    float acc[4][8];
#pragma unroll
    for (int i = 0; i < 4; i++)
#pragma unroll
        for (int j = 0; j < 8; j++) acc[i][j] = 0.f;

    for (int kt = 0; kt < 128; kt += 32) {
        __syncthreads();
#pragma unroll
        for (int j = 0; j < 8; j++) {
            int idx = j * 256 + tid;
            int r = idx >> 5;
            int k = idx & 31;
            Xs[r][k] = x[(row0 + r) * GD + kt + k] * sd[kt + k];
        }
#pragma unroll
        for (int j = 0; j < 4; j++) {
            int idx = j * 256 + tid;
            int r = idx >> 5;
            int c4 = (idx & 31) * 4;
            *(float4*)&Ws[r][c4] = *(const float4*)&W[(kt + r) * GD + c4];
        }
        __syncthreads();

#pragma unroll
        for (int k = 0; k < 32; k++) {
            float w[8];
            *(float4*)&w[0] = *(float4*)&Ws[k][tx * 8];
            *(float4*)&w[4] = *(float4*)&Ws[k][tx * 8 + 4];
#pragma unroll
            for (int i = 0; i < 4; i++) {
                float a = Xs[ty * 4 + i][k];
#pragma unroll
                for (int j = 0; j < 8; j++) acc[i][j] = fmaf(a, w[j], acc[i][j]);
            }
        }
    }

#pragma unroll
    for (int i = 0; i < 4; i++) {
        int r = row0 + ty * 4 + i;
        float* dst = &g_Y[((size_t)s * GN + r) * GD + tx * 8];
#pragma unroll
        for (int j = 0; j < 8; j++) dst[j] = f2tf32f(acc[i][j]);
    }
}

// ---------------------------------------------------------------------------
// Kernel 2: split-K main GEMM. grid 256 = 128 row-blocks x 2 K-splits, 2 CTAs/SM.
// 256 threads = 8 warps in 2(m) x 4(n); warp tile 32x32.
// ---------------------------------------------------------------------------
__global__ __launch_bounds__(256, 2) void main_gemm(const float* __restrict__ S0,
                                                    const float* __restrict__ S1,
                                                    const float* __restrict__ S2) {
    extern __shared__ float smem[];
    float* As = smem;
    float* Bs = smem + NSTAGE * A_TILE;

    const int tid = threadIdx.x;
    const int row_blk = blockIdx.x >> 1;
    const int ks = blockIdx.x & 1;
    const int block_row = row_blk * BM;

    const int wid = tid >> 5;
    const int lane = tid & 31;
    const int warp_m = wid & 1;
    const int warp_n = wid >> 1;
    const int gid = lane >> 2;
    const int tig = lane & 3;
    const int m_base = warp_m * 32;
    const int n_base = warp_n * 32;

    float acc[2][4][4];
#pragma unroll
    for (int mi = 0; mi < 2; mi++)
#pragma unroll
        for (int ni = 0; ni < 4; ni++)
#pragma unroll
            for (int q = 0; q < 4; q++) acc[mi][ni][q] = 0.f;

    auto issue_loads = [&](int stage, int kt) {
        const int gkt = ks * KT_PER + kt;
        const int s = gkt >> 8;               // 256 k-tiles per support
        const int klocal = (gkt & 255) << 5;  // *BK
        const float* Ag = (s == 0) ? S0 : (s == 1) ? S1 : S2;
        Ag += (size_t)block_row * GN + klocal;
        const float* Bg = g_Y + ((size_t)s * GN + klocal) * GD;
        float* as = As + stage * A_TILE;
        float* bs = Bs + stage * B_TILE;
#pragma unroll
        for (int j = 0; j < 2; j++) {
            int idx = j * 256 + tid;
            int r = idx >> 3;
            int c4 = (idx & 7) * 4;
            cp_async16(&as[r * ASTR + c4], Ag + (size_t)r * GN + c4);
        }
#pragma unroll
        for (int j = 0; j < 4; j++) {
            int idx = j * 256 + tid;
            int r = idx >> 5;
            int c4 = (idx & 31) * 4;
            cp_async16(&bs[r * BSTR + c4], Bg + r * GD + c4);
        }
    };

    auto compute_tile = [&](int stage) {
        const float* as = As + stage * A_TILE;
        const float* bs = Bs + stage * B_TILE;
#pragma unroll
        for (int kk = 0; kk < 4; kk++) {
            const int k0 = kk * 8;
            uint32_t a[2][4];
#pragma unroll
            for (int mi = 0; mi < 2; mi++) {
                int r = m_base + mi * 16 + gid;
                // raw fp32 bits: tensor unit truncates to tf32 (saves 32 CVTs/tile)
                a[mi][0] = __float_as_uint(as[r * ASTR + k0 + tig]);
                a[mi][1] = __float_as_uint(as[(r + 8) * ASTR + k0 + tig]);
                a[mi][2] = __float_as_uint(as[r * ASTR + k0 + tig + 4]);
                a[mi][3] = __float_as_uint(as[(r + 8) * ASTR + k0 + tig + 4]);
            }
            uint32_t b[4][2];
#pragma unroll
            for (int ni = 0; ni < 4; ni++) {
                int c = n_base + ni * 8 + gid;
                b[ni][0] = __float_as_uint(bs[(k0 + tig) * BSTR + c]);
                b[ni][1] = __float_as_uint(bs[(k0 + tig + 4) * BSTR + c]);
            }
#pragma unroll
            for (int mi = 0; mi < 2; mi++)
#pragma unroll
                for (int ni = 0; ni < 4; ni++)
                    mma_m16n8k8_tf32(acc[mi][ni], a[mi], b[ni]);
        }
    };

#pragma unroll
    for (int st = 0; st < NSTAGE - 1; st++) {
        issue_loads(st, st);
        cp_commit();
    }

    for (int kt = 0; kt < KT_PER; kt++) {
        cp_wait<NSTAGE - 2>();
        __syncthreads();
        int nxt = kt + NSTAGE - 1;
        if (nxt < KT_PER) issue_loads(nxt & (NSTAGE - 1), nxt);
        cp_commit();
        compute_tile(kt & (NSTAGE - 1));
    }

    // store split-K partials (no relu yet)
    float* P = g_P + (size_t)ks * GN * GD;
#pragma unroll
    for (int mi = 0; mi < 2; mi++) {
#pragma unroll
        for (int ni = 0; ni < 4; ni++) {
            int r = block_row + m_base + mi * 16 + gid;
            int c = n_base + ni * 8 + tig * 2;
            *(float2*)&P[(size_t)r * GD + c] =
                make_float2(acc[mi][ni][0], acc[mi][ni][1]);
            *(float2*)&P[(size_t)(r + 8) * GD + c] =
                make_float2(acc[mi][ni][2], acc[mi][ni][3]);
        }
    }
}

// ---------------------------------------------------------------------------
// Kernel 3: out = relu(P0 + P1)
// ---------------------------------------------------------------------------
__global__ __launch_bounds__(256) void reduce_relu(float* __restrict__ out) {
    const int i = blockIdx.x * 256 + threadIdx.x;  // float4 index
    const float4 a = ((const float4*)g_P)[i];
    const float4 b = ((const float4*)(g_P + (size_t)GN * GD))[i];
    float4 o;
    o.x = fmaxf(a.x + b.x, 0.f);
    o.y = fmaxf(a.y + b.y, 0.f);
    o.z = fmaxf(a.z + b.z, 0.f);
    o.w = fmaxf(a.w + b.w, 0.f);
    ((float4*)out)[i] = o;
}

// ---------------------------------------------------------------------------
extern "C" void kernel_launch(void* const* d_in, const int* in_sizes, int n_in,
                              void* d_out, int out_size) {
    const float* x = (const float*)d_in[0];
    const float* S0 = (const float*)d_in[1];
    const float* S1 = (const float*)d_in[2];
    const float* S2 = (const float*)d_in[3];
    const float* W = (const float*)d_in[4];
    const float* sd0 = (const float*)d_in[5];
    const float* sd1 = (const float*)d_in[6];
    const float* sd2 = (const float*)d_in[7];
    float* out = (float*)d_out;

    cudaFuncSetAttribute(main_gemm, cudaFuncAttributeMaxDynamicSharedMemorySize,
                         SMEM2);

    dim3 pgrid(GN / 64, 3);
    prep_kernel<<<pgrid, 256>>>(x, W, sd0, sd1, sd2);
    main_gemm<<<GN / BM * KSPLIT, 256, SMEM2>>>(S0, S1, S2);
    reduce_relu<<<GN * GD / 4 / 256, 256>>>(out);
}